// round 15
// baseline (speedup 1.0000x reference)
#include <cuda_runtime.h>
#include <cuda_bf16.h>
#include <math.h>
#include <stdint.h>

#define NUM_FIELDS 32
#define FIELD_DIM  50000
#define EMB_DIM    64
#define ATT_DIM    32
#define NPAIRS     496
#define NTH        128
#define GRID_CTAS  740

// ---- dynamic smem layout (bytes) ----
#define OFF_LUT    0       // 512 u32 packed pair offsets
#define OFF_SP     2048    // score partials: 4 planes x 520 f32 (stride-pad) = 8320
#define OFF_Q      10368   // 512 f32 (pads = 0)
#define OFF_RED    12416   // 12 f32: per-warp (mx, r, rb)
#define OFF_ET     12464   // Et[f][w]: 32 fields x 36 u32 (K-permuted bf16x2)
#define SMEM_TOTAL 17152
#define ET_FSTRIDE 144     // 36 words * 4B
#define SP_STRIDE  520     // words; kk plane shift = 8 banks

typedef unsigned long long ull;

__device__ __forceinline__ uint32_t s2u(const void* p){
    uint32_t a; asm("{ .reg .u64 t; cvta.to.shared.u64 t, %1; cvt.u32.u64 %0, t; }":"=r"(a):"l"(p)); return a;
}
__device__ __forceinline__ uint32_t bfpair(float lo, float hi){
    uint32_t r; asm("cvt.rn.bf16x2.f32 %0, %1, %2;":"=r"(r):"f"(hi),"f"(lo)); return r;
}
__device__ __forceinline__ uint32_t mulbf2(uint32_t a, uint32_t b){
    uint32_t r; asm("mul.bf16x2 %0, %1, %2;":"=r"(r):"r"(a),"r"(b)); return r;
}
__device__ __forceinline__ uint32_t lds32(uint32_t a){
    uint32_t v; asm volatile("ld.shared.b32 %0, [%1];":"=r"(v):"r"(a)); return v;
}
__device__ __forceinline__ float lds32f(uint32_t a){
    float v; asm volatile("ld.shared.b32 %0, [%1];":"=f"(v):"r"(a)); return v;
}
__device__ __forceinline__ void lds128(uint32_t a, uint32_t* v){
    asm volatile("ld.shared.v4.b32 {%0,%1,%2,%3}, [%4];"
                 :"=r"(v[0]),"=r"(v[1]),"=r"(v[2]),"=r"(v[3]):"r"(a));
}
__device__ __forceinline__ void sts64(uint32_t a, uint32_t v0, uint32_t v1){
    asm volatile("st.shared.v2.b32 [%0], {%1,%2};"::"r"(a),"r"(v0),"r"(v1):"memory");
}
__device__ __forceinline__ void sts32f(uint32_t a, float v){
    asm volatile("st.shared.b32 [%0], %1;"::"r"(a),"f"(v):"memory");
}
__device__ __forceinline__ void mma16816(float* c, uint32_t a0, uint32_t a1, uint32_t a2, uint32_t a3,
                                         uint32_t b0, uint32_t b1){
    asm volatile("mma.sync.aligned.m16n8k16.row.col.f32.bf16.bf16.f32 "
                 "{%0,%1,%2,%3}, {%4,%5,%6,%7}, {%8,%9}, {%0,%1,%2,%3};"
                 : "+f"(c[0]),"+f"(c[1]),"+f"(c[2]),"+f"(c[3])
                 : "r"(a0),"r"(a1),"r"(a2),"r"(a3),"r"(b0),"r"(b1));
}
// ---- packed f32x2 helpers ----
__device__ __forceinline__ ull pk2(float lo, float hi){
    ull r; asm("mov.b64 %0, {%1, %2};" : "=l"(r) : "f"(lo), "f"(hi)); return r;
}
__device__ __forceinline__ void upk2(ull v, float &lo, float &hi){
    asm("mov.b64 {%0, %1}, %2;" : "=f"(lo), "=f"(hi) : "l"(v));
}
__device__ __forceinline__ ull add2(ull a, ull b){
    ull d; asm("add.rn.f32x2 %0, %1, %2;" : "=l"(d) : "l"(a), "l"(b)); return d;
}
__device__ __forceinline__ void fma2(ull &d, ull a, ull b){
    asm("fma.rn.f32x2 %0, %1, %2, %0;" : "+l"(d) : "l"(a), "l"(b));
}
__device__ __forceinline__ ull and64(ull a, ull m){
    ull d; asm("and.b64 %0, %1, %2;" : "=l"(d) : "l"(a), "l"(m)); return d;
}
__device__ __forceinline__ void decode_pair(int p, int &i, int &j){
    int c = 31, ii = 0;
    while (p >= c) { p -= c; c--; ii++; }
    i = ii; j = ii + 1 + p;
}

__global__ __launch_bounds__(NTH, 5)
void afm_mma_kernel(const int*   __restrict__ x,
                    const float* __restrict__ emb,
                    const float* __restrict__ lin,
                    const float* __restrict__ lin_bias,
                    const float* __restrict__ W1,
                    const float* __restrict__ b1,
                    const float* __restrict__ w2,
                    const float* __restrict__ pw,
                    float*       __restrict__ out,
                    int BATCH)
{
    extern __shared__ char smem[];
    const uint32_t sb  = s2u(smem);
    const uint32_t etb = sb + OFF_ET;
    const int t    = threadIdx.x;
    const int wid  = t >> 5;
    const int lane = t & 31;

    float*    sSP  = (float*)(smem + OFF_SP);
    float*    sQ   = (float*)(smem + OFF_Q);
    float*    sRed = (float*)(smem + OFF_RED);
    uint32_t* sLUT = (uint32_t*)(smem + OFF_LUT);

    // ---- one-time init: pads so that sum over kk planes = -1e30 for p>=496 ----
    if (t < 16) {
        sSP[0 * SP_STRIDE + 496 + t] = -1e30f;
        sSP[1 * SP_STRIDE + 496 + t] = 0.f;
        sSP[2 * SP_STRIDE + 496 + t] = 0.f;
        sSP[3 * SP_STRIDE + 496 + t] = 0.f;
        sQ[496 + t] = 0.f;
    }
    for (int p = t; p < 512; p += NTH) {
        int pp = (p < NPAIRS) ? p : 0;
        int i, j; decode_pair(pp, i, j);
        sLUT[p] = (uint32_t)(i * ET_FSTRIDE) | ((uint32_t)(j * ET_FSTRIDE) << 16);
    }

    // ---- W1 (+ proj_w as n-tile 4) as permanent B-fragments (logical k indexing) ----
    uint32_t bfrag[5][4][2];
    {
        int n  = (lane >> 2);
        int kk = (lane & 3) * 2;
        #pragma unroll
        for (int ks = 0; ks < 4; ks++) {
            #pragma unroll
            for (int nt = 0; nt < 4; nt++) {
                int k = ks * 16 + kk, col = nt * 8 + n;
                bfrag[nt][ks][0] = bfpair(W1[(k    ) * 32 + col], W1[(k + 1) * 32 + col]);
                bfrag[nt][ks][1] = bfpair(W1[(k + 8) * 32 + col], W1[(k + 9) * 32 + col]);
            }
            int k = ks * 16 + kk;
            bfrag[4][ks][0] = (n == 0) ? bfpair(pw[k],     pw[k + 1]) : 0u;
            bfrag[4][ks][1] = (n == 0) ? bfpair(pw[k + 8], pw[k + 9]) : 0u;
        }
    }
    // packed epilogue constants: b1 pair and 0.5*w2 pair at this lane's C columns
    ull b1p[4], w2p[4];
    {
        int c0 = (lane & 3) * 2;
        #pragma unroll
        for (int nt = 0; nt < 4; nt++) {
            b1p[nt] = pk2(b1[nt * 8 + c0], b1[nt * 8 + c0 + 1]);
            w2p[nt] = pk2(0.5f * w2[nt * 8 + c0], 0.5f * w2[nt * 8 + c0 + 1]);
        }
    }
    const ull ABSM = 0x7FFFFFFF7FFFFFFFull;

    const float lbias = lin_bias[0];
    const int f = t >> 2, q4 = t & 3;
    const uint32_t ebase = etb + (uint32_t)(lane & 3) * 32;   // + 8*kk words
    const uint32_t lutb  = sb + OFF_LUT + ((uint32_t)(lane >> 2)) * 4;
    // per-lane score-partial base: plane (lane&3), row (lane>>2)
    const uint32_t spb   = sb + OFF_SP + (((uint32_t)(lane & 3)) * SP_STRIDE + (uint32_t)(lane >> 2)) * 4;

    float firstv = 0.f;
    __syncthreads();

    for (int b = blockIdx.x; b < BATCH; b += gridDim.x) {
        // ---- gather embeddings -> K-permuted bf16x2 SMEM (no reg prefetch; cross-CTA overlap hides it) ----
        {
            int id = x[b * NUM_FIELDS + f] + f * FIELD_DIM;
            const float4* src = (const float4*)(emb + (size_t)id * EMB_DIM + q4 * 16);
            float4 v0 = src[0], v1 = src[1], v2 = src[2], v3 = src[3];
            uint32_t wb = etb + ((uint32_t)f * 36 + 2u * q4) * 4;
            sts64(wb,       bfpair(v0.x, v0.y), bfpair(v2.x, v2.y));
            sts64(wb + 32,  bfpair(v0.z, v0.w), bfpair(v2.z, v2.w));
            sts64(wb + 64,  bfpair(v1.x, v1.y), bfpair(v3.x, v3.y));
            sts64(wb + 96,  bfpair(v1.z, v1.w), bfpair(v3.z, v3.w));
        }
        if (t < 32) {   // first-order linear term (fp32 exact)
            float v = lin[x[b * NUM_FIELDS + t] + t * FIELD_DIM];
            #pragma unroll
            for (int off = 16; off; off >>= 1) v += __shfl_down_sync(0xffffffffu, v, off);
            if (t == 0) firstv = v + lbias;
        }
        __syncthreads();                                   // S1

        // ---- 8 M-tiles per warp (interleaved across warps), 5 N-tiles ----
        #pragma unroll
        for (int tl = 0; tl < 8; tl++) {
            const int base_t = (tl * 4 + wid) * 16;
            if (base_t >= NPAIRS) continue;                // tile 31 (tl=7,wid=3) = pure padding
            uint32_t lo = lutb + (uint32_t)base_t * 4;
            uint32_t po1 = lds32(lo), po2 = lds32(lo + 32);

            uint32_t P1[8], P2[8];
            {
                uint32_t E[16];
                uint32_t ai = ebase + (po1 & 0xffffu), aj = ebase + (po1 >> 16);
                lds128(ai, E); lds128(ai + 16, E + 4);
                lds128(aj, E + 8); lds128(aj + 16, E + 12);
                #pragma unroll
                for (int c = 0; c < 8; c++) P1[c] = mulbf2(E[c], E[8 + c]);
                ai = ebase + (po2 & 0xffffu); aj = ebase + (po2 >> 16);
                lds128(ai, E); lds128(ai + 16, E + 4);
                lds128(aj, E + 8); lds128(aj + 16, E + 12);
                #pragma unroll
                for (int c = 0; c < 8; c++) P2[c] = mulbf2(E[c], E[8 + c]);
            }

            float acc[5][4];
            #pragma unroll
            for (int nt = 0; nt < 5; nt++)
                #pragma unroll
                for (int v = 0; v < 4; v++) acc[nt][v] = 0.f;

            #pragma unroll
            for (int ks = 0; ks < 4; ks++) {
                #pragma unroll
                for (int nt = 0; nt < 5; nt++)
                    mma16816(acc[nt], P1[2*ks], P2[2*ks], P1[2*ks+1], P2[2*ks+1],
                             bfrag[nt][ks][0], bfrag[nt][ks][1]);
            }

            // packed epilogue -> per-lane kk-partial, NO shfl (deferred reduction)
            #pragma unroll
            for (int rh = 0; rh < 2; rh++) {
                ull spa = 0ull, spb2 = 0ull;
                {
                    ull t2, u2;
                    t2 = add2(pk2(acc[0][rh*2], acc[0][rh*2+1]), b1p[0]);
                    u2 = add2(t2, and64(t2, ABSM)); fma2(spa, w2p[0], u2);
                    t2 = add2(pk2(acc[2][rh*2], acc[2][rh*2+1]), b1p[2]);
                    u2 = add2(t2, and64(t2, ABSM)); fma2(spb2, w2p[2], u2);
                    t2 = add2(pk2(acc[1][rh*2], acc[1][rh*2+1]), b1p[1]);
                    u2 = add2(t2, and64(t2, ABSM)); fma2(spa, w2p[1], u2);
                    t2 = add2(pk2(acc[3][rh*2], acc[3][rh*2+1]), b1p[3]);
                    u2 = add2(t2, and64(t2, ABSM)); fma2(spb2, w2p[3], u2);
                }
                float slo, shi; upk2(add2(spa, spb2), slo, shi);
                float spv = slo + shi;
                sts32f(spb + (uint32_t)(base_t + rh * 8) * 4, spv);
                if ((lane & 3) == 0)
                    sts32f(sb + OFF_Q + (uint32_t)(base_t + rh * 8 + (lane >> 2)) * 4,
                           acc[4][rh * 2]);
            }
        }
        __syncthreads();                                   // S2

        // ---- per-warp softmax partials: sum 4 kk planes, own-max shift ----
        {
            uint32_t a0 = sb + OFF_SP + (uint32_t)t * 4;
            float s0, s1, s2, s3;
            {
                float p00 = lds32f(a0),                  p10 = lds32f(a0 + 512),
                      p20 = lds32f(a0 + 1024),           p30 = lds32f(a0 + 1536);
                uint32_t a1 = a0 + SP_STRIDE * 4;
                float p01 = lds32f(a1),                  p11 = lds32f(a1 + 512),
                      p21 = lds32f(a1 + 1024),           p31 = lds32f(a1 + 1536);
                uint32_t a2 = a1 + SP_STRIDE * 4;
                float p02 = lds32f(a2),                  p12 = lds32f(a2 + 512),
                      p22 = lds32f(a2 + 1024),           p32 = lds32f(a2 + 1536);
                uint32_t a3 = a2 + SP_STRIDE * 4;
                float p03 = lds32f(a3),                  p13 = lds32f(a3 + 512),
                      p23 = lds32f(a3 + 1024),           p33 = lds32f(a3 + 1536);
                s0 = (p00 + p01) + (p02 + p03);
                s1 = (p10 + p11) + (p12 + p13);
                s2 = (p20 + p21) + (p22 + p23);
                s3 = (p30 + p31) + (p32 + p33);
            }
            float q0 = sQ[t], q1 = sQ[t + 128], q2 = sQ[t + 256], q3 = sQ[t + 384];
            float m = fmaxf(fmaxf(s0, s1), fmaxf(s2, s3));
            #pragma unroll
            for (int off = 16; off; off >>= 1) m = fmaxf(m, __shfl_xor_sync(0xffffffffu, m, off));
            float e0 = __expf(s0 - m), e1 = __expf(s1 - m);
            float e2 = __expf(s2 - m), e3 = __expf(s3 - m);
            float r  = (e0 + e1) + (e2 + e3);
            float rb = fmaf(e0, q0, fmaf(e1, q1, fmaf(e2, q2, e3 * q3)));
            #pragma unroll
            for (int off = 16; off; off >>= 1) {
                r  += __shfl_xor_sync(0xffffffffu, r,  off);
                rb += __shfl_xor_sync(0xffffffffu, rb, off);
            }
            if (lane == 0) { sRed[wid * 3] = m; sRed[wid * 3 + 1] = r; sRed[wid * 3 + 2] = rb; }
        }
        __syncthreads();                                   // S3

        if (t == 0) {
            float MX = fmaxf(fmaxf(sRed[0], sRed[3]), fmaxf(sRed[6], sRed[9]));
            float R = 0.f, RB = 0.f;
            #pragma unroll
            for (int w = 0; w < 4; w++) {
                float sc = __expf(sRed[w * 3] - MX);
                R  = fmaf(sRed[w * 3 + 1], sc, R);
                RB = fmaf(sRed[w * 3 + 2], sc, RB);
            }
            float y = firstv + RB / R;
            out[b] = 1.f / (1.f + __expf(-y));
        }
    }
}

extern "C" void kernel_launch(void* const* d_in, const int* in_sizes, int n_in,
                              void* d_out, int out_size)
{
    const int*   x   = (const int*)  d_in[0];
    const float* emb = (const float*)d_in[1];
    const float* lin = (const float*)d_in[2];
    const float* lb  = (const float*)d_in[3];
    const float* W1  = (const float*)d_in[4];
    const float* b1  = (const float*)d_in[5];
    const float* w2  = (const float*)d_in[6];
    const float* pwv = (const float*)d_in[7];
    const int B = in_sizes[0] / NUM_FIELDS;

    cudaFuncSetAttribute(afm_mma_kernel, cudaFuncAttributeMaxDynamicSharedMemorySize, SMEM_TOTAL);
    int grid = GRID_CTAS < B ? GRID_CTAS : B;
    afm_mma_kernel<<<grid, NTH, SMEM_TOTAL>>>(x, emb, lin, lb, W1, b1, w2, pwv, (float*)d_out, B);
}

// round 16
// speedup vs baseline: 1.0446x; 1.0446x over previous
#include <cuda_runtime.h>
#include <cuda_bf16.h>
#include <math.h>
#include <stdint.h>

#define NUM_FIELDS 32
#define FIELD_DIM  50000
#define EMB_DIM    64
#define ATT_DIM    32
#define NPAIRS     496
#define NTH        128
#define GRID_CTAS  592

// ---- dynamic smem layout (bytes) ----
#define OFF_LUT    0       // 512 u32 packed pair offsets
#define OFF_SP     2048    // score partials: 4 planes x 520 f32 (stride-pad) = 8320
#define OFF_Q      10368   // 512 f32 (pads = 0)
#define OFF_RED    12416   // 12 f32: per-warp (mx, r, rb)
#define OFF_ET     12464   // 2 x (32 fields x 36 u32 K-permuted bf16x2) ping-pong
#define ET_BUFSZ   4608
#define SMEM_TOTAL 21680
#define ET_FSTRIDE 144     // 36 words * 4B
#define SP_STRIDE  520     // words; kk plane shift = 8 banks

typedef unsigned long long ull;

__device__ __forceinline__ uint32_t s2u(const void* p){
    uint32_t a; asm("{ .reg .u64 t; cvta.to.shared.u64 t, %1; cvt.u32.u64 %0, t; }":"=r"(a):"l"(p)); return a;
}
__device__ __forceinline__ uint32_t bfpair(float lo, float hi){
    uint32_t r; asm("cvt.rn.bf16x2.f32 %0, %1, %2;":"=r"(r):"f"(hi),"f"(lo)); return r;
}
__device__ __forceinline__ uint32_t mulbf2(uint32_t a, uint32_t b){
    uint32_t r; asm("mul.bf16x2 %0, %1, %2;":"=r"(r):"r"(a),"r"(b)); return r;
}
__device__ __forceinline__ uint32_t lds32(uint32_t a){
    uint32_t v; asm volatile("ld.shared.b32 %0, [%1];":"=r"(v):"r"(a)); return v;
}
__device__ __forceinline__ float lds32f(uint32_t a){
    float v; asm volatile("ld.shared.b32 %0, [%1];":"=f"(v):"r"(a)); return v;
}
__device__ __forceinline__ void lds128(uint32_t a, uint32_t* v){
    asm volatile("ld.shared.v4.b32 {%0,%1,%2,%3}, [%4];"
                 :"=r"(v[0]),"=r"(v[1]),"=r"(v[2]),"=r"(v[3]):"r"(a));
}
__device__ __forceinline__ void sts64(uint32_t a, uint32_t v0, uint32_t v1){
    asm volatile("st.shared.v2.b32 [%0], {%1,%2};"::"r"(a),"r"(v0),"r"(v1):"memory");
}
__device__ __forceinline__ void sts32f(uint32_t a, float v){
    asm volatile("st.shared.b32 [%0], %1;"::"r"(a),"f"(v):"memory");
}
__device__ __forceinline__ void mma16816(float* c, uint32_t a0, uint32_t a1, uint32_t a2, uint32_t a3,
                                         uint32_t b0, uint32_t b1){
    asm volatile("mma.sync.aligned.m16n8k16.row.col.f32.bf16.bf16.f32 "
                 "{%0,%1,%2,%3}, {%4,%5,%6,%7}, {%8,%9}, {%0,%1,%2,%3};"
                 : "+f"(c[0]),"+f"(c[1]),"+f"(c[2]),"+f"(c[3])
                 : "r"(a0),"r"(a1),"r"(a2),"r"(a3),"r"(b0),"r"(b1));
}
// ---- packed f32x2 helpers ----
__device__ __forceinline__ ull pk2(float lo, float hi){
    ull r; asm("mov.b64 %0, {%1, %2};" : "=l"(r) : "f"(lo), "f"(hi)); return r;
}
__device__ __forceinline__ void upk2(ull v, float &lo, float &hi){
    asm("mov.b64 {%0, %1}, %2;" : "=f"(lo), "=f"(hi) : "l"(v));
}
__device__ __forceinline__ ull add2(ull a, ull b){
    ull d; asm("add.rn.f32x2 %0, %1, %2;" : "=l"(d) : "l"(a), "l"(b)); return d;
}
__device__ __forceinline__ void fma2(ull &d, ull a, ull b){
    asm("fma.rn.f32x2 %0, %1, %2, %0;" : "+l"(d) : "l"(a), "l"(b));
}
__device__ __forceinline__ ull and64(ull a, ull m){
    ull d; asm("and.b64 %0, %1, %2;" : "=l"(d) : "l"(a), "l"(m)); return d;
}
__device__ __forceinline__ void decode_pair(int p, int &i, int &j){
    int c = 31, ii = 0;
    while (p >= c) { p -= c; c--; ii++; }
    i = ii; j = ii + 1 + p;
}

__global__ __launch_bounds__(NTH, 4)
void afm_mma_kernel(const int*   __restrict__ x,
                    const float* __restrict__ emb,
                    const float* __restrict__ lin,
                    const float* __restrict__ lin_bias,
                    const float* __restrict__ W1,
                    const float* __restrict__ b1,
                    const float* __restrict__ w2,
                    const float* __restrict__ pw,
                    float*       __restrict__ out,
                    int BATCH)
{
    extern __shared__ char smem[];
    const uint32_t sb  = s2u(smem);
    const uint32_t etb = sb + OFF_ET;
    const int t    = threadIdx.x;
    const int wid  = t >> 5;
    const int lane = t & 31;

    float*    sSP  = (float*)(smem + OFF_SP);
    float*    sQ   = (float*)(smem + OFF_Q);
    float*    sRed = (float*)(smem + OFF_RED);
    uint32_t* sLUT = (uint32_t*)(smem + OFF_LUT);

    // ---- one-time init: pads so that sum over kk planes = -1e30 for p>=496 ----
    if (t < 16) {
        sSP[0 * SP_STRIDE + 496 + t] = -1e30f;
        sSP[1 * SP_STRIDE + 496 + t] = 0.f;
        sSP[2 * SP_STRIDE + 496 + t] = 0.f;
        sSP[3 * SP_STRIDE + 496 + t] = 0.f;
        sQ[496 + t] = 0.f;
    }
    for (int p = t; p < 512; p += NTH) {
        int pp = (p < NPAIRS) ? p : 0;
        int i, j; decode_pair(pp, i, j);
        sLUT[p] = (uint32_t)(i * ET_FSTRIDE) | ((uint32_t)(j * ET_FSTRIDE) << 16);
    }

    // ---- W1 (+ proj_w as n-tile 4) as permanent B-fragments (logical k indexing) ----
    uint32_t bfrag[5][4][2];
    {
        int n  = (lane >> 2);
        int kk = (lane & 3) * 2;
        #pragma unroll
        for (int ks = 0; ks < 4; ks++) {
            #pragma unroll
            for (int nt = 0; nt < 4; nt++) {
                int k = ks * 16 + kk, col = nt * 8 + n;
                bfrag[nt][ks][0] = bfpair(W1[(k    ) * 32 + col], W1[(k + 1) * 32 + col]);
                bfrag[nt][ks][1] = bfpair(W1[(k + 8) * 32 + col], W1[(k + 9) * 32 + col]);
            }
            int k = ks * 16 + kk;
            bfrag[4][ks][0] = (n == 0) ? bfpair(pw[k],     pw[k + 1]) : 0u;
            bfrag[4][ks][1] = (n == 0) ? bfpair(pw[k + 8], pw[k + 9]) : 0u;
        }
    }
    // packed epilogue constants: b1 pair and 0.5*w2 pair at this lane's C columns
    ull b1p[4], w2p[4];
    {
        int c0 = (lane & 3) * 2;
        #pragma unroll
        for (int nt = 0; nt < 4; nt++) {
            b1p[nt] = pk2(b1[nt * 8 + c0], b1[nt * 8 + c0 + 1]);
            w2p[nt] = pk2(0.5f * w2[nt * 8 + c0], 0.5f * w2[nt * 8 + c0 + 1]);
        }
    }
    const ull ABSM = 0x7FFFFFFF7FFFFFFFull;

    const float lbias = lin_bias[0];
    const int f = t >> 2, q4 = t & 3;
    const uint32_t lutb = sb + OFF_LUT + ((uint32_t)(lane >> 2)) * 4;
    const uint32_t spb  = sb + OFF_SP + (((uint32_t)(lane & 3)) * SP_STRIDE + (uint32_t)(lane >> 2)) * 4;
    const uint32_t wboff = ((uint32_t)f * 36 + 2u * q4) * 4;   // Et store offset within buffer

    // ---- preload sample b0 and store into buf 0 ----
    float4 pf0, pf1, pf2, pf3; float lv_next = 0.f, lv_cur = 0.f;
    {
        int id = x[blockIdx.x * NUM_FIELDS + f] + f * FIELD_DIM;
        const float4* src = (const float4*)(emb + (size_t)id * EMB_DIM + q4 * 16);
        pf0 = src[0]; pf1 = src[1]; pf2 = src[2]; pf3 = src[3];
        if (t < 32) lv_cur = lin[x[blockIdx.x * NUM_FIELDS + t] + t * FIELD_DIM];
        uint32_t wb = etb + wboff;
        sts64(wb,       bfpair(pf0.x, pf0.y), bfpair(pf2.x, pf2.y));
        sts64(wb + 32,  bfpair(pf0.z, pf0.w), bfpair(pf2.z, pf2.w));
        sts64(wb + 64,  bfpair(pf1.x, pf1.y), bfpair(pf3.x, pf3.y));
        sts64(wb + 96,  bfpair(pf1.z, pf1.w), bfpair(pf3.z, pf3.w));
    }
    __syncthreads();

    uint32_t cur = 0;
    for (int b = blockIdx.x; b < BATCH; b += gridDim.x, cur ^= 1) {
        // ---- prefetch next sample into registers (lands during tile loop) ----
        const int nb = b + gridDim.x;
        if (nb < BATCH) {
            int id = x[nb * NUM_FIELDS + f] + f * FIELD_DIM;
            const float4* src = (const float4*)(emb + (size_t)id * EMB_DIM + q4 * 16);
            pf0 = src[0]; pf1 = src[1]; pf2 = src[2]; pf3 = src[3];
            if (t < 32) lv_next = lin[x[nb * NUM_FIELDS + t] + t * FIELD_DIM];
        }

        // ---- 8 M-tiles per warp from buf[cur], 5 N-tiles ----
        const uint32_t ebase = etb + cur * ET_BUFSZ + (uint32_t)(lane & 3) * 32;
        #pragma unroll
        for (int tl = 0; tl < 8; tl++) {
            const int base_t = (tl * 4 + wid) * 16;
            if (base_t >= NPAIRS) continue;                // tile 31 (tl=7,wid=3) = pure padding
            uint32_t lo = lutb + (uint32_t)base_t * 4;
            uint32_t po1 = lds32(lo), po2 = lds32(lo + 32);

            uint32_t P1[8], P2[8];
            {
                uint32_t E[16];
                uint32_t ai = ebase + (po1 & 0xffffu), aj = ebase + (po1 >> 16);
                lds128(ai, E); lds128(ai + 16, E + 4);
                lds128(aj, E + 8); lds128(aj + 16, E + 12);
                #pragma unroll
                for (int c = 0; c < 8; c++) P1[c] = mulbf2(E[c], E[8 + c]);
                ai = ebase + (po2 & 0xffffu); aj = ebase + (po2 >> 16);
                lds128(ai, E); lds128(ai + 16, E + 4);
                lds128(aj, E + 8); lds128(aj + 16, E + 12);
                #pragma unroll
                for (int c = 0; c < 8; c++) P2[c] = mulbf2(E[c], E[8 + c]);
            }

            float acc[5][4];
            #pragma unroll
            for (int nt = 0; nt < 5; nt++)
                #pragma unroll
                for (int v = 0; v < 4; v++) acc[nt][v] = 0.f;

            #pragma unroll
            for (int ks = 0; ks < 4; ks++) {
                #pragma unroll
                for (int nt = 0; nt < 5; nt++)
                    mma16816(acc[nt], P1[2*ks], P2[2*ks], P1[2*ks+1], P2[2*ks+1],
                             bfrag[nt][ks][0], bfrag[nt][ks][1]);
            }

            // packed epilogue -> per-lane kk-partial, NO shfl (deferred reduction)
            #pragma unroll
            for (int rh = 0; rh < 2; rh++) {
                ull spa = 0ull, spb2 = 0ull;
                {
                    ull t2, u2;
                    t2 = add2(pk2(acc[0][rh*2], acc[0][rh*2+1]), b1p[0]);
                    u2 = add2(t2, and64(t2, ABSM)); fma2(spa, w2p[0], u2);
                    t2 = add2(pk2(acc[2][rh*2], acc[2][rh*2+1]), b1p[2]);
                    u2 = add2(t2, and64(t2, ABSM)); fma2(spb2, w2p[2], u2);
                    t2 = add2(pk2(acc[1][rh*2], acc[1][rh*2+1]), b1p[1]);
                    u2 = add2(t2, and64(t2, ABSM)); fma2(spa, w2p[1], u2);
                    t2 = add2(pk2(acc[3][rh*2], acc[3][rh*2+1]), b1p[3]);
                    u2 = add2(t2, and64(t2, ABSM)); fma2(spb2, w2p[3], u2);
                }
                float slo, shi; upk2(add2(spa, spb2), slo, shi);
                float spv = slo + shi;
                sts32f(spb + (uint32_t)(base_t + rh * 8) * 4, spv);
                if ((lane & 3) == 0)
                    sts32f(sb + OFF_Q + (uint32_t)(base_t + rh * 8 + (lane >> 2)) * 4,
                           acc[4][rh * 2]);
            }
        }

        // ---- store prefetched sample into buf[cur^1] (overlapped; ordered by S2) ----
        if (nb < BATCH) {
            uint32_t wb = etb + (cur ^ 1u) * ET_BUFSZ + wboff;
            sts64(wb,       bfpair(pf0.x, pf0.y), bfpair(pf2.x, pf2.y));
            sts64(wb + 32,  bfpair(pf0.z, pf0.w), bfpair(pf2.z, pf2.w));
            sts64(wb + 64,  bfpair(pf1.x, pf1.y), bfpair(pf3.x, pf3.y));
            sts64(wb + 96,  bfpair(pf1.z, pf1.w), bfpair(pf3.z, pf3.w));
        }
        __syncthreads();                                   // S2

        // ---- per-warp softmax partials: sum 4 kk planes, own-max shift ----
        float firstv = 0.f;
        {
            uint32_t a0 = sb + OFF_SP + (uint32_t)t * 4;
            float s0, s1, s2, s3;
            {
                float p00 = lds32f(a0),                  p10 = lds32f(a0 + 512),
                      p20 = lds32f(a0 + 1024),           p30 = lds32f(a0 + 1536);
                uint32_t a1 = a0 + SP_STRIDE * 4;
                float p01 = lds32f(a1),                  p11 = lds32f(a1 + 512),
                      p21 = lds32f(a1 + 1024),           p31 = lds32f(a1 + 1536);
                uint32_t a2 = a1 + SP_STRIDE * 4;
                float p02 = lds32f(a2),                  p12 = lds32f(a2 + 512),
                      p22 = lds32f(a2 + 1024),           p32 = lds32f(a2 + 1536);
                uint32_t a3 = a2 + SP_STRIDE * 4;
                float p03 = lds32f(a3),                  p13 = lds32f(a3 + 512),
                      p23 = lds32f(a3 + 1024),           p33 = lds32f(a3 + 1536);
                s0 = (p00 + p01) + (p02 + p03);
                s1 = (p10 + p11) + (p12 + p13);
                s2 = (p20 + p21) + (p22 + p23);
                s3 = (p30 + p31) + (p32 + p33);
            }
            float q0 = sQ[t], q1 = sQ[t + 128], q2 = sQ[t + 256], q3 = sQ[t + 384];
            float m = fmaxf(fmaxf(s0, s1), fmaxf(s2, s3));
            #pragma unroll
            for (int off = 16; off; off >>= 1) m = fmaxf(m, __shfl_xor_sync(0xffffffffu, m, off));
            float e0 = __expf(s0 - m), e1 = __expf(s1 - m);
            float e2 = __expf(s2 - m), e3 = __expf(s3 - m);
            float r  = (e0 + e1) + (e2 + e3);
            float rb = fmaf(e0, q0, fmaf(e1, q1, fmaf(e2, q2, e3 * q3)));
            #pragma unroll
            for (int off = 16; off; off >>= 1) {
                r  += __shfl_xor_sync(0xffffffffu, r,  off);
                rb += __shfl_xor_sync(0xffffffffu, rb, off);
            }
            if (lane == 0) { sRed[wid * 3] = m; sRed[wid * 3 + 1] = r; sRed[wid * 3 + 2] = rb; }
        }
        if (t < 32) {   // first-order linear term for CURRENT sample (warp 0, off main path)
            float v = lv_cur;
            #pragma unroll
            for (int off = 16; off; off >>= 1) v += __shfl_down_sync(0xffffffffu, v, off);
            firstv = v + lbias;
        }
        __syncthreads();                                   // S3

        if (t == 0) {
            float MX = fmaxf(fmaxf(sRed[0], sRed[3]), fmaxf(sRed[6], sRed[9]));
            float R = 0.f, RB = 0.f;
            #pragma unroll
            for (int w = 0; w < 4; w++) {
                float sc = __expf(sRed[w * 3] - MX);
                R  = fmaf(sRed[w * 3 + 1], sc, R);
                RB = fmaf(sRed[w * 3 + 2], sc, RB);
            }
            float y = firstv + RB / R;
            out[b] = 1.f / (1.f + __expf(-y));
        }
        lv_cur = lv_next;
    }
}

extern "C" void kernel_launch(void* const* d_in, const int* in_sizes, int n_in,
                              void* d_out, int out_size)
{
    const int*   x   = (const int*)  d_in[0];
    const float* emb = (const float*)d_in[1];
    const float* lin = (const float*)d_in[2];
    const float* lb  = (const float*)d_in[3];
    const float* W1  = (const float*)d_in[4];
    const float* b1  = (const float*)d_in[5];
    const float* w2  = (const float*)d_in[6];
    const float* pwv = (const float*)d_in[7];
    const int B = in_sizes[0] / NUM_FIELDS;

    cudaFuncSetAttribute(afm_mma_kernel, cudaFuncAttributeMaxDynamicSharedMemorySize, SMEM_TOTAL);
    int grid = GRID_CTAS < B ? GRID_CTAS : B;
    afm_mma_kernel<<<grid, NTH, SMEM_TOTAL>>>(x, emb, lin, lb, W1, b1, w2, pwv, (float*)d_out, B);
}

// round 17
// speedup vs baseline: 1.1015x; 1.0545x over previous
#include <cuda_runtime.h>
#include <cuda_bf16.h>
#include <math.h>
#include <stdint.h>

#define NUM_FIELDS 32
#define FIELD_DIM  50000
#define EMB_DIM    64
#define ATT_DIM    32
#define NPAIRS     496
#define NTH        128
#define GRID_CTAS  592

// ---- dynamic smem layout (bytes) ----
#define OFF_LUT    0       // 512 u32 packed pair offsets
#define OFF_SP     2048    // score partials: 4 planes x 520 f32 (stride-pad) = 8320
#define OFF_Q      10368   // 512 f32 (pads = 0)
#define OFF_RED    12416   // 2 x 12 f32 double-buffered per-warp (mx, r, rb)
#define OFF_ET     12544   // Et[f][w]: 32 fields x 36 u32 (K-permuted bf16x2)
#define SMEM_TOTAL 17152
#define ET_FSTRIDE 144     // 36 words * 4B
#define SP_STRIDE  520     // words; kk plane shift = 8 banks

typedef unsigned long long ull;

__device__ __forceinline__ uint32_t s2u(const void* p){
    uint32_t a; asm("{ .reg .u64 t; cvta.to.shared.u64 t, %1; cvt.u32.u64 %0, t; }":"=r"(a):"l"(p)); return a;
}
__device__ __forceinline__ uint32_t bfpair(float lo, float hi){
    uint32_t r; asm("cvt.rn.bf16x2.f32 %0, %1, %2;":"=r"(r):"f"(hi),"f"(lo)); return r;
}
__device__ __forceinline__ uint32_t mulbf2(uint32_t a, uint32_t b){
    uint32_t r; asm("mul.bf16x2 %0, %1, %2;":"=r"(r):"r"(a),"r"(b)); return r;
}
__device__ __forceinline__ uint32_t lds32(uint32_t a){
    uint32_t v; asm volatile("ld.shared.b32 %0, [%1];":"=r"(v):"r"(a)); return v;
}
__device__ __forceinline__ float lds32f(uint32_t a){
    float v; asm volatile("ld.shared.b32 %0, [%1];":"=f"(v):"r"(a)); return v;
}
__device__ __forceinline__ void lds128(uint32_t a, uint32_t* v){
    asm volatile("ld.shared.v4.b32 {%0,%1,%2,%3}, [%4];"
                 :"=r"(v[0]),"=r"(v[1]),"=r"(v[2]),"=r"(v[3]):"r"(a));
}
__device__ __forceinline__ void sts64(uint32_t a, uint32_t v0, uint32_t v1){
    asm volatile("st.shared.v2.b32 [%0], {%1,%2};"::"r"(a),"r"(v0),"r"(v1):"memory");
}
__device__ __forceinline__ void sts32f(uint32_t a, float v){
    asm volatile("st.shared.b32 [%0], %1;"::"r"(a),"f"(v):"memory");
}
__device__ __forceinline__ void mma16816(float* c, uint32_t a0, uint32_t a1, uint32_t a2, uint32_t a3,
                                         uint32_t b0, uint32_t b1){
    asm volatile("mma.sync.aligned.m16n8k16.row.col.f32.bf16.bf16.f32 "
                 "{%0,%1,%2,%3}, {%4,%5,%6,%7}, {%8,%9}, {%0,%1,%2,%3};"
                 : "+f"(c[0]),"+f"(c[1]),"+f"(c[2]),"+f"(c[3])
                 : "r"(a0),"r"(a1),"r"(a2),"r"(a3),"r"(b0),"r"(b1));
}
// ---- packed f32x2 helpers ----
__device__ __forceinline__ ull pk2(float lo, float hi){
    ull r; asm("mov.b64 %0, {%1, %2};" : "=l"(r) : "f"(lo), "f"(hi)); return r;
}
__device__ __forceinline__ void upk2(ull v, float &lo, float &hi){
    asm("mov.b64 {%0, %1}, %2;" : "=f"(lo), "=f"(hi) : "l"(v));
}
__device__ __forceinline__ ull add2(ull a, ull b){
    ull d; asm("add.rn.f32x2 %0, %1, %2;" : "=l"(d) : "l"(a), "l"(b)); return d;
}
__device__ __forceinline__ void fma2(ull &d, ull a, ull b){
    asm("fma.rn.f32x2 %0, %1, %2, %0;" : "+l"(d) : "l"(a), "l"(b));
}
__device__ __forceinline__ ull and64(ull a, ull m){
    ull d; asm("and.b64 %0, %1, %2;" : "=l"(d) : "l"(a), "l"(m)); return d;
}
__device__ __forceinline__ void decode_pair(int p, int &i, int &j){
    int c = 31, ii = 0;
    while (p >= c) { p -= c; c--; ii++; }
    i = ii; j = ii + 1 + p;
}

__global__ __launch_bounds__(NTH, 4)
void afm_mma_kernel(const int*   __restrict__ x,
                    const float* __restrict__ emb,
                    const float* __restrict__ lin,
                    const float* __restrict__ lin_bias,
                    const float* __restrict__ W1,
                    const float* __restrict__ b1,
                    const float* __restrict__ w2,
                    const float* __restrict__ pw,
                    float*       __restrict__ out,
                    int BATCH)
{
    extern __shared__ char smem[];
    const uint32_t sb  = s2u(smem);
    const uint32_t etb = sb + OFF_ET;
    const int t    = threadIdx.x;
    const int wid  = t >> 5;
    const int lane = t & 31;

    float*    sSP  = (float*)(smem + OFF_SP);
    float*    sQ   = (float*)(smem + OFF_Q);
    float*    sRed = (float*)(smem + OFF_RED);
    uint32_t* sLUT = (uint32_t*)(smem + OFF_LUT);

    // ---- one-time init: pads so that sum over kk planes = -1e30 for p>=496 ----
    if (t < 16) {
        sSP[0 * SP_STRIDE + 496 + t] = -1e30f;
        sSP[1 * SP_STRIDE + 496 + t] = 0.f;
        sSP[2 * SP_STRIDE + 496 + t] = 0.f;
        sSP[3 * SP_STRIDE + 496 + t] = 0.f;
        sQ[496 + t] = 0.f;
    }
    for (int p = t; p < 512; p += NTH) {
        int pp = (p < NPAIRS) ? p : 0;
        int i, j; decode_pair(pp, i, j);
        sLUT[p] = (uint32_t)(i * ET_FSTRIDE) | ((uint32_t)(j * ET_FSTRIDE) << 16);
    }

    // ---- W1 (+ proj_w as n-tile 4) as permanent B-fragments (logical k indexing) ----
    uint32_t bfrag[5][4][2];
    {
        int n  = (lane >> 2);
        int kk = (lane & 3) * 2;
        #pragma unroll
        for (int ks = 0; ks < 4; ks++) {
            #pragma unroll
            for (int nt = 0; nt < 4; nt++) {
                int k = ks * 16 + kk, col = nt * 8 + n;
                bfrag[nt][ks][0] = bfpair(W1[(k    ) * 32 + col], W1[(k + 1) * 32 + col]);
                bfrag[nt][ks][1] = bfpair(W1[(k + 8) * 32 + col], W1[(k + 9) * 32 + col]);
            }
            int k = ks * 16 + kk;
            bfrag[4][ks][0] = (n == 0) ? bfpair(pw[k],     pw[k + 1]) : 0u;
            bfrag[4][ks][1] = (n == 0) ? bfpair(pw[k + 8], pw[k + 9]) : 0u;
        }
    }
    // packed epilogue constants: b1 pair and 0.5*w2 pair at this lane's C columns
    ull b1p[4], w2p[4];
    {
        int c0 = (lane & 3) * 2;
        #pragma unroll
        for (int nt = 0; nt < 4; nt++) {
            b1p[nt] = pk2(b1[nt * 8 + c0], b1[nt * 8 + c0 + 1]);
            w2p[nt] = pk2(0.5f * w2[nt * 8 + c0], 0.5f * w2[nt * 8 + c0 + 1]);
        }
    }
    const ull ABSM = 0x7FFFFFFF7FFFFFFFull;

    const float lbias = lin_bias[0];
    const int f = t >> 2, q4 = t & 3;
    const uint32_t ebase = etb + (uint32_t)(lane & 3) * 32;   // + 8*kk words
    const uint32_t lutb  = sb + OFF_LUT + ((uint32_t)(lane >> 2)) * 4;
    const uint32_t spb   = sb + OFF_SP + (((uint32_t)(lane & 3)) * SP_STRIDE + (uint32_t)(lane >> 2)) * 4;

    // ---- prefetch first sample: 16 floats per thread (4 threads/field) ----
    float4 pf0, pf1, pf2, pf3; float pfl = 0.f;
    {
        int id = x[blockIdx.x * NUM_FIELDS + f] + f * FIELD_DIM;
        const float4* src = (const float4*)(emb + (size_t)id * EMB_DIM + q4 * 16);
        pf0 = src[0]; pf1 = src[1]; pf2 = src[2]; pf3 = src[3];
        if (t < 32) pfl = lin[x[blockIdx.x * NUM_FIELDS + t] + t * FIELD_DIM];
    }
    float firstv = 0.f, firstv_prev = 0.f;
    int b_prev = -1;
    uint32_t rbuf = 0;
    __syncthreads();

    for (int b = blockIdx.x; b < BATCH; b += gridDim.x, rbuf ^= 1) {
        // ---- store prefetched embeddings, K-permuted (phys word = 8*(l&3) + l/4) ----
        {
            uint32_t wb = etb + ((uint32_t)f * 36 + 2u * q4) * 4;
            sts64(wb,       bfpair(pf0.x, pf0.y), bfpair(pf2.x, pf2.y));
            sts64(wb + 32,  bfpair(pf0.z, pf0.w), bfpair(pf2.z, pf2.w));
            sts64(wb + 64,  bfpair(pf1.x, pf1.y), bfpair(pf3.x, pf3.y));
            sts64(wb + 96,  bfpair(pf1.z, pf1.w), bfpair(pf3.z, pf3.w));
        }
        if (t < 32) {   // first-order linear term (fp32 exact)
            float v = pfl;
            #pragma unroll
            for (int off = 16; off; off >>= 1) v += __shfl_down_sync(0xffffffffu, v, off);
            if (t == 0) firstv = v + lbias;
        }
        __syncthreads();                                   // S1

        // ---- deferred final combine for PREVIOUS sample (t0 only; overlaps tile loop) ----
        if (t == 0 && b_prev >= 0) {
            const float* rp = sRed + (rbuf ^ 1u) * 12;
            float MX = fmaxf(fmaxf(rp[0], rp[3]), fmaxf(rp[6], rp[9]));
            float R = 0.f, RB = 0.f;
            #pragma unroll
            for (int w = 0; w < 4; w++) {
                float sc = __expf(rp[w * 3] - MX);
                R  = fmaf(rp[w * 3 + 1], sc, R);
                RB = fmaf(rp[w * 3 + 2], sc, RB);
            }
            float y = firstv_prev + RB / R;
            out[b_prev] = 1.f / (1.f + __expf(-y));
        }

        // ---- prefetch next sample (hidden behind compute) ----
        {
            int nb = b + gridDim.x;
            if (nb < BATCH) {
                int id = x[nb * NUM_FIELDS + f] + f * FIELD_DIM;
                const float4* src = (const float4*)(emb + (size_t)id * EMB_DIM + q4 * 16);
                pf0 = src[0]; pf1 = src[1]; pf2 = src[2]; pf3 = src[3];
                if (t < 32) pfl = lin[x[nb * NUM_FIELDS + t] + t * FIELD_DIM];
            }
        }

        // ---- 8 M-tiles per warp (interleaved across warps), 5 N-tiles ----
        #pragma unroll
        for (int tl = 0; tl < 8; tl++) {
            const int base_t = (tl * 4 + wid) * 16;
            if (base_t >= NPAIRS) continue;                // tile 31 (tl=7,wid=3) = pure padding
            uint32_t lo = lutb + (uint32_t)base_t * 4;
            uint32_t po1 = lds32(lo), po2 = lds32(lo + 32);

            uint32_t P1[8], P2[8];
            {
                uint32_t E[16];
                uint32_t ai = ebase + (po1 & 0xffffu), aj = ebase + (po1 >> 16);
                lds128(ai, E); lds128(ai + 16, E + 4);
                lds128(aj, E + 8); lds128(aj + 16, E + 12);
                #pragma unroll
                for (int c = 0; c < 8; c++) P1[c] = mulbf2(E[c], E[8 + c]);
                ai = ebase + (po2 & 0xffffu); aj = ebase + (po2 >> 16);
                lds128(ai, E); lds128(ai + 16, E + 4);
                lds128(aj, E + 8); lds128(aj + 16, E + 12);
                #pragma unroll
                for (int c = 0; c < 8; c++) P2[c] = mulbf2(E[c], E[8 + c]);
            }

            float acc[5][4];
            #pragma unroll
            for (int nt = 0; nt < 5; nt++)
                #pragma unroll
                for (int v = 0; v < 4; v++) acc[nt][v] = 0.f;

            #pragma unroll
            for (int ks = 0; ks < 4; ks++) {
                #pragma unroll
                for (int nt = 0; nt < 5; nt++)
                    mma16816(acc[nt], P1[2*ks], P2[2*ks], P1[2*ks+1], P2[2*ks+1],
                             bfrag[nt][ks][0], bfrag[nt][ks][1]);
            }

            // packed epilogue -> per-lane kk-partial, NO shfl (deferred reduction)
            #pragma unroll
            for (int rh = 0; rh < 2; rh++) {
                ull spa = 0ull, spb2 = 0ull;
                {
                    ull t2, u2;
                    t2 = add2(pk2(acc[0][rh*2], acc[0][rh*2+1]), b1p[0]);
                    u2 = add2(t2, and64(t2, ABSM)); fma2(spa, w2p[0], u2);
                    t2 = add2(pk2(acc[2][rh*2], acc[2][rh*2+1]), b1p[2]);
                    u2 = add2(t2, and64(t2, ABSM)); fma2(spb2, w2p[2], u2);
                    t2 = add2(pk2(acc[1][rh*2], acc[1][rh*2+1]), b1p[1]);
                    u2 = add2(t2, and64(t2, ABSM)); fma2(spa, w2p[1], u2);
                    t2 = add2(pk2(acc[3][rh*2], acc[3][rh*2+1]), b1p[3]);
                    u2 = add2(t2, and64(t2, ABSM)); fma2(spb2, w2p[3], u2);
                }
                float slo, shi; upk2(add2(spa, spb2), slo, shi);
                float spv = slo + shi;
                sts32f(spb + (uint32_t)(base_t + rh * 8) * 4, spv);
                if ((lane & 3) == 0)
                    sts32f(sb + OFF_Q + (uint32_t)(base_t + rh * 8 + (lane >> 2)) * 4,
                           acc[4][rh * 2]);
            }
        }
        __syncthreads();                                   // S2

        // ---- per-warp softmax partials: sum 4 kk planes, own-max shift -> sRed[rbuf] ----
        {
            uint32_t a0 = sb + OFF_SP + (uint32_t)t * 4;
            float s0, s1, s2, s3;
            {
                float p00 = lds32f(a0),                  p10 = lds32f(a0 + 512),
                      p20 = lds32f(a0 + 1024),           p30 = lds32f(a0 + 1536);
                uint32_t a1 = a0 + SP_STRIDE * 4;
                float p01 = lds32f(a1),                  p11 = lds32f(a1 + 512),
                      p21 = lds32f(a1 + 1024),           p31 = lds32f(a1 + 1536);
                uint32_t a2 = a1 + SP_STRIDE * 4;
                float p02 = lds32f(a2),                  p12 = lds32f(a2 + 512),
                      p22 = lds32f(a2 + 1024),           p32 = lds32f(a2 + 1536);
                uint32_t a3 = a2 + SP_STRIDE * 4;
                float p03 = lds32f(a3),                  p13 = lds32f(a3 + 512),
                      p23 = lds32f(a3 + 1024),           p33 = lds32f(a3 + 1536);
                s0 = (p00 + p01) + (p02 + p03);
                s1 = (p10 + p11) + (p12 + p13);
                s2 = (p20 + p21) + (p22 + p23);
                s3 = (p30 + p31) + (p32 + p33);
            }
            float q0 = sQ[t], q1 = sQ[t + 128], q2 = sQ[t + 256], q3 = sQ[t + 384];
            float m = fmaxf(fmaxf(s0, s1), fmaxf(s2, s3));
            #pragma unroll
            for (int off = 16; off; off >>= 1) m = fmaxf(m, __shfl_xor_sync(0xffffffffu, m, off));
            float e0 = __expf(s0 - m), e1 = __expf(s1 - m);
            float e2 = __expf(s2 - m), e3 = __expf(s3 - m);
            float r  = (e0 + e1) + (e2 + e3);
            float rb = fmaf(e0, q0, fmaf(e1, q1, fmaf(e2, q2, e3 * q3)));
            #pragma unroll
            for (int off = 16; off; off >>= 1) {
                r  += __shfl_xor_sync(0xffffffffu, r,  off);
                rb += __shfl_xor_sync(0xffffffffu, rb, off);
            }
            if (lane == 0) {
                float* rp = sRed + rbuf * 12;
                rp[wid * 3] = m; rp[wid * 3 + 1] = r; rp[wid * 3 + 2] = rb;
            }
        }
        // no S3: combine for this sample happens next iteration (or in the tail)
        firstv_prev = firstv;
        b_prev = b;
    }

    // ---- tail: combine the final sample ----
    __syncthreads();
    if (t == 0 && b_prev >= 0) {
        const float* rp = sRed + (rbuf ^ 1u) * 12;
        float MX = fmaxf(fmaxf(rp[0], rp[3]), fmaxf(rp[6], rp[9]));
        float R = 0.f, RB = 0.f;
        #pragma unroll
        for (int w = 0; w < 4; w++) {
            float sc = __expf(rp[w * 3] - MX);
            R  = fmaf(rp[w * 3 + 1], sc, R);
            RB = fmaf(rp[w * 3 + 2], sc, RB);
        }
        float y = firstv_prev + RB / R;
        out[b_prev] = 1.f / (1.f + __expf(-y));
    }
}

extern "C" void kernel_launch(void* const* d_in, const int* in_sizes, int n_in,
                              void* d_out, int out_size)
{
    const int*   x   = (const int*)  d_in[0];
    const float* emb = (const float*)d_in[1];
    const float* lin = (const float*)d_in[2];
    const float* lb  = (const float*)d_in[3];
    const float* W1  = (const float*)d_in[4];
    const float* b1  = (const float*)d_in[5];
    const float* w2  = (const float*)d_in[6];
    const float* pwv = (const float*)d_in[7];
    const int B = in_sizes[0] / NUM_FIELDS;

    cudaFuncSetAttribute(afm_mma_kernel, cudaFuncAttributeMaxDynamicSharedMemorySize, SMEM_TOTAL);
    int grid = GRID_CTAS < B ? GRID_CTAS : B;
    afm_mma_kernel<<<grid, NTH, SMEM_TOTAL>>>(x, emb, lin, lb, W1, b1, w2, pwv, (float*)d_out, B);
}